// round 14
// baseline (speedup 1.0000x reference)
#include <cuda_runtime.h>
#include <math.h>
#include <stdint.h>

// CantorMoELayer — B=8, P=2048, D=1024, E=16, S=64, DK=128, H=16
// R14: all three GEMVs (gate, V, rec) now TF32 mma.sync with fragment-ordered
// repacked weights. xn stored as TF32 in smem (A-frags load with zero cvt);
// V stored dual (fp32 for Vp, TF32 for rec A-frags). Gate runs on one warp
// per expert slot; V-tile tables rebalance the gate warp's load.

namespace {

constexpr int P_  = 2048;
constexpr int D_  = 1024;
constexpr int E_  = 16;
constexpr int S_  = 64;
constexpr int DK_ = 128;
constexpr int H_  = 16;

constexpr int XN_STR = 68;
constexpr int V_STR  = 132;
constexpr int RC_STR = 68;

__device__ __forceinline__ float sigm(float x) { return 1.0f / (1.0f + expf(-x)); }
__device__ __forceinline__ float gelu_exact(float x) {
    return 0.5f * x * (1.0f + erff(x * 0.70710678118654752440f));
}
__device__ __forceinline__ uint32_t tf32(float f) {
    uint32_t r;
    asm("cvt.rna.tf32.f32 %0, %1;" : "=r"(r) : "f"(f));
    return r;
}
__device__ __forceinline__ void mma_m16n8k8(
    float& c0, float& c1, float& c2, float& c3,
    uint32_t a0, uint32_t a1, uint32_t a2, uint32_t a3,
    uint32_t b0, uint32_t b1)
{
    asm("mma.sync.aligned.m16n8k8.row.col.f32.tf32.tf32.f32 "
        "{%0,%1,%2,%3},{%4,%5,%6,%7},{%8,%9},{%0,%1,%2,%3};"
        : "+f"(c0), "+f"(c1), "+f"(c2), "+f"(c3)
        : "r"(a0), "r"(a1), "r"(a2), "r"(a3), "r"(b0), "r"(b1));
}

__device__ __forceinline__ void pick(float fp, int& nact, int& e0, int& e1) {
    nact = 0; e0 = 0; e1 = -1;
    const int base = (int)floorf(fp * 16.0f);
#pragma unroll
    for (int dd = -1; dd <= 1; ++dd) {
        const int ee = base + dd;
        if (ee < 0 || ee >= E_) continue;
        const float fmn = fmaxf(0.0f, (float)ee * 0.0625f - 0.03125f);
        const float fmx = fminf(1.0f, (float)(ee + 1) * 0.0625f + 0.03125f);
        if (fp >= fmn && fp < fmx) {
            if (nact == 0) e0 = ee; else if (nact == 1) e1 = ee;
            ++nact;
        }
    }
    if (nact > 2) nact = 2;
    if (nact < 2) e1 = -1;
}

// fragment-ordered TF32 weight scratch
// wv : [e][nt=16][kt=8][lane]  b0=B[kt*8+tig][nt*8+gid], b1=B[kt*8+tig+4][...]
// wout:[e][nt=8][kt=16][lane]
// w1 : [e][nt=2][kt=8][lane]
__device__ uint2 g_frag_wv[E_ * 16 * 8 * 32];
__device__ uint2 g_frag_wo[E_ * 8 * 16 * 32];
__device__ uint2 g_frag_w1[E_ * 2 * 8 * 32];

__global__ void __launch_bounds__(256) repack_kernel(
    const float* __restrict__ wv, const float* __restrict__ wout,
    const float* __restrict__ w1)
{
    const int i = blockIdx.x * 256 + threadIdx.x;   // 65536 threads
    const int lane = i & 31;
    const int gid = lane >> 2, tig = lane & 3;
    {   // wv: i = ((e*16 + nt)*8 + kt)*32 + lane
        const int kt = (i >> 5) & 7;
        const int nt = (i >> 8) & 15;
        const int e  = i >> 12;
        const float v0 = __ldg(wv + e * (S_ * DK_) + (kt * 8 + tig)     * DK_ + nt * 8 + gid);
        const float v1 = __ldg(wv + e * (S_ * DK_) + (kt * 8 + tig + 4) * DK_ + nt * 8 + gid);
        g_frag_wv[i] = make_uint2(tf32(v0), tf32(v1));
    }
    {   // wout: i = ((e*8 + nt)*16 + kt)*32 + lane
        const int kt = (i >> 5) & 15;
        const int nt = (i >> 9) & 7;
        const int e  = i >> 12;
        const float v0 = __ldg(wout + e * (DK_ * S_) + (kt * 8 + tig)     * S_ + nt * 8 + gid);
        const float v1 = __ldg(wout + e * (DK_ * S_) + (kt * 8 + tig + 4) * S_ + nt * 8 + gid);
        g_frag_wo[i] = make_uint2(tf32(v0), tf32(v1));
    }
    if (i < E_ * 2 * 8 * 32) {   // w1: i = ((e*2 + nt)*8 + kt)*32 + lane
        const int kt = (i >> 5) & 7;
        const int nt = (i >> 8) & 1;
        const int e  = i >> 9;
        const float v0 = __ldg(w1 + e * (S_ * H_) + (kt * 8 + tig)     * H_ + nt * 8 + gid);
        const float v1 = __ldg(w1 + e * (S_ * H_) + (kt * 8 + tig + 4) * H_ + nt * 8 + gid);
        g_frag_w1[i] = make_uint2(tf32(v0), tf32(v1));
    }
}

__global__ void __launch_bounds__(256, 4) cantor_moe_kernel(
    const float* __restrict__ x,
    const float* __restrict__ fingerprints,
    const float* __restrict__ ln_gamma,
    const float* __restrict__ ln_beta,
    const float* __restrict__ b1,
    const float* __restrict__ w2,
    const float* __restrict__ b2,
    const float* __restrict__ alpha,
    const float* __restrict__ penta,
    const float* __restrict__ betas,
    const float* __restrict__ pos_embed,
    const float* __restrict__ temperature,
    float* __restrict__ out)
{
    __shared__ __align__(16) uint32_t xnsm[2][8][XN_STR];   // TF32 normalized slices
    __shared__ __align__(16) float    Vsm[2][8][V_STR];     // fp32 V (for Vp)
    __shared__ __align__(16) uint32_t VFsm[2][8][V_STR];    // TF32 V (rec A-frags)
    __shared__ __align__(16) float    recsm[2][8][RC_STR];
    __shared__ float scalesm[2][8];
    __shared__ float Vpsm[2][8][5];
    __shared__ float w_esm[2];

    const int p    = blockIdx.x;
    const int tid  = threadIdx.x;
    const int warp = tid >> 5;
    const int lane = tid & 31;
    const int gid  = lane >> 2;
    const int tig  = lane & 3;

    int nact, e0, e1;
    pick(__ldg(fingerprints + p), nact, e0, e1);

    // ---------------- LayerNorm: warp w = batch b; 2-pass; TF32 out ----------------
    {
        const int b = warp;
        const float* xr = x + ((size_t)b * P_ + p) * D_;
        float s = 0.f, ss = 0.f;
#pragma unroll
        for (int it = 0; it < 8; ++it) {
            const float4 xv = __ldg((const float4*)xr + it * 32 + lane);
            s  += xv.x + xv.y + xv.z + xv.w;
            ss += xv.x * xv.x + xv.y * xv.y + xv.z * xv.z + xv.w * xv.w;
        }
#pragma unroll
        for (int o = 16; o; o >>= 1) {
            s  += __shfl_xor_sync(~0u, s, o);
            ss += __shfl_xor_sync(~0u, ss, o);
        }
        const float mu   = s * (1.0f / D_);
        const float var  = ss * (1.0f / D_) - mu * mu;
        const float rstd = rsqrtf(var + 1e-5f);
        const int kk = lane >> 4;
        if (kk < nact) {
            const int ee = kk ? e1 : e0;
            const int f4 = ee * 16 + (lane & 15);
            const float4 xv = __ldg((const float4*)xr + f4);
            const float4 gm = __ldg((const float4*)ln_gamma + f4);
            const float4 bt = __ldg((const float4*)ln_beta + f4);
            uint4 o4;
            o4.x = tf32((xv.x - mu) * rstd * gm.x + bt.x);
            o4.y = tf32((xv.y - mu) * rstd * gm.y + bt.y);
            o4.z = tf32((xv.z - mu) * rstd * gm.z + bt.z);
            o4.w = tf32((xv.w - mu) * rstd * gm.w + bt.w);
            *(uint4*)&xnsm[kk][b][(lane & 15) * 4] = o4;
        }
    }
    __syncthreads();   // sync1

    const int nw = (nact == 2) ? 4 : 8;
    const int k  = (nact == 2) ? (warp >> 2) : 0;
    const int wq = (nact == 2) ? (warp & 3) : warp;
    const int e  = k ? e1 : e0;

    // ---------------- phase 2: A-frags, gate MMA (wq==0), V MMA ----------------
    {
        uint32_t A0[8], A2[8];
#pragma unroll
        for (int kt = 0; kt < 8; ++kt) {
            A0[kt] = xnsm[k][gid][kt * 8 + tig];
            A2[kt] = xnsm[k][gid][kt * 8 + tig + 4];
        }

        if (wq == 0) {   // gate: h = xn @ w1; scale = sigm(gelu(h)·w2+b2)*aw+(1-aw)
            const uint2* FW1 = g_frag_w1 + e * (2 * 8 * 32);
            float t = 0.f;
#pragma unroll
            for (int nt = 0; nt < 2; ++nt) {
                float c0 = 0.f, c1 = 0.f, c2 = 0.f, c3 = 0.f;
#pragma unroll
                for (int kt = 0; kt < 8; ++kt) {
                    const uint2 bb = __ldg(FW1 + (nt * 8 + kt) * 32 + lane);
                    mma_m16n8k8(c0, c1, c2, c3, A0[kt], 0u, A2[kt], 0u, bb.x, bb.y);
                }
                const int j0 = nt * 8 + 2 * tig;
                const float2 b1v = __ldg((const float2*)(b1 + e * H_ + j0));
                const float2 w2v = __ldg((const float2*)(w2 + e * H_ + j0));
                t += gelu_exact(c0 + b1v.x) * w2v.x + gelu_exact(c1 + b1v.y) * w2v.y;
            }
            t += __shfl_down_sync(~0u, t, 2, 4);
            t += __shfl_down_sync(~0u, t, 1, 4);
            if (tig == 0) {
                const float gate = sigm(t + __ldg(b2 + e));
                const float aw   = sigm(__ldg(alpha + e));
                scalesm[k][gid] = gate * aw + (1.0f - aw);
            }
        }

        // V tiles, rebalanced so the gate warp carries fewer chains
        int vstart, vcnt;
        if (nact == 2) {
            const int sarr[4] = {0, 2, 6, 11};
            const int carr[4] = {2, 4, 5, 5};
            vstart = sarr[wq]; vcnt = carr[wq];
        } else {
            const int sarr[8] = {0, 1, 3, 5, 7, 9, 11, 13};
            const int carr[8] = {1, 2, 2, 2, 2, 2, 2, 3};
            vstart = sarr[wq]; vcnt = carr[wq];
        }
        const uint2* FWV = g_frag_wv + e * (16 * 8 * 32);
        for (int ni = 0; ni < vcnt; ++ni) {
            const int nt = vstart + ni;
            float c0 = 0.f, c1 = 0.f, c2 = 0.f, c3 = 0.f;
#pragma unroll
            for (int kt = 0; kt < 8; ++kt) {
                const uint2 bb = __ldg(FWV + (nt * 8 + kt) * 32 + lane);
                mma_m16n8k8(c0, c1, c2, c3, A0[kt], 0u, A2[kt], 0u, bb.x, bb.y);
            }
            *(float2*)&Vsm[k][gid][nt * 8 + 2 * tig] = make_float2(c0, c1);
            *(uint2*)&VFsm[k][gid][nt * 8 + 2 * tig] = make_uint2(tf32(c0), tf32(c1));
        }
    }
    __syncthreads();   // sync2

    // ---------------- rec = V @ wout via MMA; then Vp + w_e ----------------
    {
        const uint2* FWO = g_frag_wo + e * (8 * 16 * 32);
        const float sc = scalesm[k][gid];
        const int ntpw = 8 / nw;
        for (int ni = 0; ni < ntpw; ++ni) {
            const int nt = wq * ntpw + ni;
            float c0 = 0.f, c1 = 0.f, c2 = 0.f, c3 = 0.f;
#pragma unroll
            for (int kt = 0; kt < 16; ++kt) {
                const uint32_t a0 = VFsm[k][gid][kt * 8 + tig];
                const uint32_t a2 = VFsm[k][gid][kt * 8 + tig + 4];
                const uint2 bb = __ldg(FWO + (nt * 16 + kt) * 32 + lane);
                mma_m16n8k8(c0, c1, c2, c3, a0, 0u, a2, 0u, bb.x, bb.y);
            }
            *(float2*)&recsm[k][gid][nt * 8 + 2 * tig] = make_float2(c0 * sc, c1 * sc);
        }

        const int dpw = 40 / nw;
        for (int t = 0; t < dpw; ++t) {
            const int idx = wq * dpw + t;
            const int v = idx >> 3, b = idx & 7;
            const float4 pv = __ldg((const float4*)(penta + (e * 5 + v) * DK_) + lane);
            const float4 vv = *(const float4*)&Vsm[k][b][lane * 4];
            float pd = pv.x * vv.x + pv.y * vv.y + pv.z * vv.z + pv.w * vv.w;
            float nn = pv.x * pv.x + pv.y * pv.y + pv.z * pv.z + pv.w * pv.w;
#pragma unroll
            for (int o = 16; o; o >>= 1) {
                pd += __shfl_xor_sync(~0u, pd, o);
                nn += __shfl_xor_sync(~0u, nn, o);
            }
            if (lane == 0)
                Vpsm[k][b][v] = pd * rsqrtf(nn) * scalesm[k][b];
        }
        if (wq == 0) {
            const float4 pe = __ldg((const float4*)(pos_embed + e * DK_) + lane);
            float pm = pe.x + pe.y + pe.z + pe.w;
#pragma unroll
            for (int o = 16; o; o >>= 1) pm += __shfl_xor_sync(~0u, pm, o);
            if (lane == 0) {
                float sb = 0.f, cnt = 0.f;
#pragma unroll
                for (int kk = 0; kk < 4; ++kk) {
                    const int off = (kk == 0) ? -2 : (kk == 1) ? -1 : (kk == 2) ? 1 : 2;
                    const int nb = e + off;
                    if (nb >= 0 && nb < E_) { sb += sigm(__ldg(betas + e * 4 + kk)); cnt += 1.f; }
                }
                w_esm[k] = sigm(pm * (1.0f / DK_)) * (1.0f + sb / cnt);
            }
        }
    }
    __syncthreads();   // sync3

    // -------- epilogue --------
    {
        const int b = tid >> 5;
        float den = 0.f;
        for (int kk = 0; kk < nact; ++kk) den += w_esm[kk];
        den = fmaxf(den, 1e-6f);
        float fs = 0.f;
#pragma unroll
        for (int v = 0; v < 5; ++v) {
            float nv = 0.f;
            for (int kk = 0; kk < nact; ++kk) nv += Vpsm[kk][b][v] * w_esm[kk];
            fs += nv;
        }
        const float fused = (fs / den) * 0.2f / fabsf(__ldg(temperature));

        const float* xr  = x   + ((size_t)b * P_ + p) * D_;
        float*       orw = out + ((size_t)b * P_ + p) * D_;
#pragma unroll
        for (int it = 0; it < 8; ++it) {
            const int f4 = it * 32 + lane;
            float4 xv = __ldg((const float4*)xr + f4);
            const int ee = f4 >> 4;
            const int kk = (ee == e0) ? 0 : ((ee == e1) ? 1 : -1);
            if (kk >= 0) {
                const int si = (f4 & 15) * 4;
                const float4 rv = *(const float4*)&recsm[kk][b][si];
                xv.x += fused * rv.x;
                xv.y += fused * rv.y;
                xv.z += fused * rv.z;
                xv.w += fused * rv.w;
            }
            ((float4*)orw)[f4] = xv;
        }
    }
}

} // namespace

extern "C" void kernel_launch(void* const* d_in, const int* in_sizes, int n_in,
                              void* d_out, int out_size)
{
    (void)in_sizes; (void)n_in; (void)out_size;
    repack_kernel<<<256, 256>>>(
        (const float*)d_in[9],   // wv
        (const float*)d_in[12],  // wout
        (const float*)d_in[4]);  // w1
    cantor_moe_kernel<<<P_, 256>>>(
        (const float*)d_in[0],   // x
        (const float*)d_in[1],   // fingerprints
        (const float*)d_in[2],   // ln_gamma
        (const float*)d_in[3],   // ln_beta
        (const float*)d_in[5],   // b1
        (const float*)d_in[6],   // w2
        (const float*)d_in[7],   // b2
        (const float*)d_in[8],   // alpha
        (const float*)d_in[10],  // penta
        (const float*)d_in[11],  // betas
        (const float*)d_in[13],  // pos_embed
        (const float*)d_in[14],  // temperature
        (float*)d_out);
}

// round 16
// speedup vs baseline: 1.3508x; 1.3508x over previous
#include <cuda_runtime.h>
#include <math.h>
#include <stdint.h>

// CantorMoELayer — B=8, P=2048, D=1024, E=16, S=64, DK=128, H=16
// R15: exact R12 (best, 76.3us) + ONE change: V phase dual-stores V as fp32
// (Vsm, for Vp dots) and TF32 (VFsm, for rec A-fragments), removing the 32
// cvt.rna per rec chain that dominated R12's 21% ALU. No other deltas.

namespace {

constexpr int P_  = 2048;
constexpr int D_  = 1024;
constexpr int E_  = 16;
constexpr int S_  = 64;
constexpr int DK_ = 128;
constexpr int H_  = 16;

constexpr int XN_STR = 68;
constexpr int V_STR  = 132;
constexpr int RC_STR = 68;

__device__ __forceinline__ float sigm(float x) { return 1.0f / (1.0f + expf(-x)); }
__device__ __forceinline__ float gelu_exact(float x) {
    return 0.5f * x * (1.0f + erff(x * 0.70710678118654752440f));
}
__device__ __forceinline__ uint32_t tf32(float f) {
    uint32_t r;
    asm("cvt.rna.tf32.f32 %0, %1;" : "=r"(r) : "f"(f));
    return r;
}
__device__ __forceinline__ void mma_m16n8k8(
    float& c0, float& c1, float& c2, float& c3,
    uint32_t a0, uint32_t a1, uint32_t a2, uint32_t a3,
    uint32_t b0, uint32_t b1)
{
    asm("mma.sync.aligned.m16n8k8.row.col.f32.tf32.tf32.f32 "
        "{%0,%1,%2,%3},{%4,%5,%6,%7},{%8,%9},{%0,%1,%2,%3};"
        : "+f"(c0), "+f"(c1), "+f"(c2), "+f"(c3)
        : "r"(a0), "r"(a1), "r"(a2), "r"(a3), "r"(b0), "r"(b1));
}

__device__ __forceinline__ void pick(float fp, int& nact, int& e0, int& e1) {
    nact = 0; e0 = 0; e1 = -1;
    const int base = (int)floorf(fp * 16.0f);
#pragma unroll
    for (int dd = -1; dd <= 1; ++dd) {
        const int ee = base + dd;
        if (ee < 0 || ee >= E_) continue;
        const float fmn = fmaxf(0.0f, (float)ee * 0.0625f - 0.03125f);
        const float fmx = fminf(1.0f, (float)(ee + 1) * 0.0625f + 0.03125f);
        if (fp >= fmn && fp < fmx) {
            if (nact == 0) e0 = ee; else if (nact == 1) e1 = ee;
            ++nact;
        }
    }
    if (nact > 2) nact = 2;
    if (nact < 2) e1 = -1;
}

// fragment-ordered TF32 weight scratch (1 MB total)
__device__ uint2 g_frag_wv[E_ * 16 * 8 * 32];
__device__ uint2 g_frag_wo[E_ * 8 * 16 * 32];

__global__ void __launch_bounds__(256) repack_kernel(
    const float* __restrict__ wv, const float* __restrict__ wout)
{
    const int i = blockIdx.x * 256 + threadIdx.x;   // 65536 threads
    const int lane = i & 31;
    const int gid = lane >> 2, tig = lane & 3;
    {   // wv: i = ((e*16 + nt)*8 + kt)*32 + lane
        const int kt = (i >> 5) & 7;
        const int nt = (i >> 8) & 15;
        const int e  = i >> 12;
        const float v0 = __ldg(wv + e * (S_ * DK_) + (kt * 8 + tig)     * DK_ + nt * 8 + gid);
        const float v1 = __ldg(wv + e * (S_ * DK_) + (kt * 8 + tig + 4) * DK_ + nt * 8 + gid);
        g_frag_wv[i] = make_uint2(tf32(v0), tf32(v1));
    }
    {   // wout: i = ((e*8 + nt)*16 + kt)*32 + lane
        const int kt = (i >> 5) & 15;
        const int nt = (i >> 9) & 7;
        const int e  = i >> 12;
        const float v0 = __ldg(wout + e * (DK_ * S_) + (kt * 8 + tig)     * S_ + nt * 8 + gid);
        const float v1 = __ldg(wout + e * (DK_ * S_) + (kt * 8 + tig + 4) * S_ + nt * 8 + gid);
        g_frag_wo[i] = make_uint2(tf32(v0), tf32(v1));
    }
}

__global__ void __launch_bounds__(256, 4) cantor_moe_kernel(
    const float* __restrict__ x,
    const float* __restrict__ fingerprints,
    const float* __restrict__ ln_gamma,
    const float* __restrict__ ln_beta,
    const float* __restrict__ w1,
    const float* __restrict__ b1,
    const float* __restrict__ w2,
    const float* __restrict__ b2,
    const float* __restrict__ alpha,
    const float* __restrict__ penta,
    const float* __restrict__ betas,
    const float* __restrict__ pos_embed,
    const float* __restrict__ temperature,
    float* __restrict__ out)
{
    __shared__ __align__(16) float    xnsm[2][8][XN_STR];
    __shared__ __align__(16) float    Vsm[2][8][V_STR];     // fp32 V (Vp dots)
    __shared__ __align__(16) uint32_t VFsm[2][8][V_STR];    // TF32 V (rec A-frags)
    __shared__ __align__(16) float    recsm[2][8][RC_STR];
    __shared__ float scalesm[2][8];
    __shared__ float Vpsm[2][8][5];
    __shared__ float w_esm[2];

    const int p    = blockIdx.x;
    const int tid  = threadIdx.x;
    const int warp = tid >> 5;
    const int lane = tid & 31;
    const int gid  = lane >> 2;
    const int tig  = lane & 3;

    int nact, e0, e1;
    pick(__ldg(fingerprints + p), nact, e0, e1);

    // ---------------- LayerNorm: warp w = batch b; 2-pass ----------------
    {
        const int b = warp;
        const float* xr = x + ((size_t)b * P_ + p) * D_;
        float s = 0.f, ss = 0.f;
#pragma unroll
        for (int it = 0; it < 8; ++it) {
            const float4 xv = __ldg((const float4*)xr + it * 32 + lane);
            s  += xv.x + xv.y + xv.z + xv.w;
            ss += xv.x * xv.x + xv.y * xv.y + xv.z * xv.z + xv.w * xv.w;
        }
#pragma unroll
        for (int o = 16; o; o >>= 1) {
            s  += __shfl_xor_sync(~0u, s, o);
            ss += __shfl_xor_sync(~0u, ss, o);
        }
        const float mu   = s * (1.0f / D_);
        const float var  = ss * (1.0f / D_) - mu * mu;
        const float rstd = rsqrtf(var + 1e-5f);
        const int kk = lane >> 4;
        if (kk < nact) {
            const int ee = kk ? e1 : e0;
            const int f4 = ee * 16 + (lane & 15);
            const float4 xv = __ldg((const float4*)xr + f4);
            const float4 gm = __ldg((const float4*)ln_gamma + f4);
            const float4 bt = __ldg((const float4*)ln_beta + f4);
            float4 o4;
            o4.x = (xv.x - mu) * rstd * gm.x + bt.x;
            o4.y = (xv.y - mu) * rstd * gm.y + bt.y;
            o4.z = (xv.z - mu) * rstd * gm.z + bt.z;
            o4.w = (xv.w - mu) * rstd * gm.w + bt.w;
            *(float4*)&xnsm[kk][b][(lane & 15) * 4] = o4;
        }
    }
    __syncthreads();   // sync1

    const int nw = (nact == 2) ? 4 : 8;
    const int k  = (nact == 2) ? (warp >> 2) : 0;
    const int wq = (nact == 2) ? (warp & 3) : warp;
    const int e  = k ? e1 : e0;

    // ---------------- gate (fp32) ----------------
    {
        const int k2 = tid >> 7, g = tid & 127;
        if (k2 < nact) {
            const int eg = k2 ? e1 : e0;
            const int b = g >> 4, j = g & 15;
            const float* W1 = w1 + eg * (S_ * H_);
            float acc = __ldg(b1 + eg * H_ + j);
#pragma unroll
            for (int s4 = 0; s4 < 16; ++s4) {
                const float4 xf = *(const float4*)&xnsm[k2][b][s4 * 4];
                acc += xf.x * __ldg(W1 + (s4 * 4 + 0) * H_ + j)
                     + xf.y * __ldg(W1 + (s4 * 4 + 1) * H_ + j)
                     + xf.z * __ldg(W1 + (s4 * 4 + 2) * H_ + j)
                     + xf.w * __ldg(W1 + (s4 * 4 + 3) * H_ + j);
            }
            float t = gelu_exact(acc) * __ldg(w2 + eg * H_ + j);
#pragma unroll
            for (int o = 8; o; o >>= 1) t += __shfl_down_sync(~0u, t, o, 16);
            if (j == 0) {
                const float gate = sigm(t + __ldg(b2 + eg));
                const float aw   = sigm(__ldg(alpha + eg));
                scalesm[k2][b] = gate * aw + (1.0f - aw);
            }
        }
    }

    // ---------------- V = feats @ wv via TF32 MMA (frag-ordered B) ----------------
    {
        uint32_t A0[8], A2[8];
#pragma unroll
        for (int kt = 0; kt < 8; ++kt) {
            A0[kt] = tf32(xnsm[k][gid][kt * 8 + tig]);
            A2[kt] = tf32(xnsm[k][gid][kt * 8 + tig + 4]);
        }
        const uint2* FWV = g_frag_wv + e * (16 * 8 * 32);
        const int ntpw = 16 / nw;
        for (int ni = 0; ni < ntpw; ++ni) {
            const int nt = wq * ntpw + ni;
            float c0 = 0.f, c1 = 0.f, c2 = 0.f, c3 = 0.f;
#pragma unroll
            for (int kt = 0; kt < 8; ++kt) {
                const uint2 bb = __ldg(FWV + (nt * 8 + kt) * 32 + lane);
                mma_m16n8k8(c0, c1, c2, c3, A0[kt], 0u, A2[kt], 0u, bb.x, bb.y);
            }
            *(float2*)&Vsm[k][gid][nt * 8 + 2 * tig] = make_float2(c0, c1);
            *(uint2*)&VFsm[k][gid][nt * 8 + 2 * tig] = make_uint2(tf32(c0), tf32(c1));
        }
    }
    __syncthreads();   // sync2

    // ---------------- rec = V @ wout via MMA (A-frags from VFsm, no cvt) ----------------
    {
        const uint2* FWO = g_frag_wo + e * (8 * 16 * 32);
        const float sc = scalesm[k][gid];
        const int ntpw = 8 / nw;
        for (int ni = 0; ni < ntpw; ++ni) {
            const int nt = wq * ntpw + ni;
            float c0 = 0.f, c1 = 0.f, c2 = 0.f, c3 = 0.f;
#pragma unroll
            for (int kt = 0; kt < 16; ++kt) {
                const uint32_t a0 = VFsm[k][gid][kt * 8 + tig];
                const uint32_t a2 = VFsm[k][gid][kt * 8 + tig + 4];
                const uint2 bb = __ldg(FWO + (nt * 16 + kt) * 32 + lane);
                mma_m16n8k8(c0, c1, c2, c3, a0, 0u, a2, 0u, bb.x, bb.y);
            }
            *(float2*)&recsm[k][gid][nt * 8 + 2 * tig] = make_float2(c0 * sc, c1 * sc);
        }

        const int dpw = 40 / nw;
        for (int t = 0; t < dpw; ++t) {
            const int idx = wq * dpw + t;
            const int v = idx >> 3, b = idx & 7;
            const float4 pv = __ldg((const float4*)(penta + (e * 5 + v) * DK_) + lane);
            const float4 vv = *(const float4*)&Vsm[k][b][lane * 4];
            float pd = pv.x * vv.x + pv.y * vv.y + pv.z * vv.z + pv.w * vv.w;
            float nn = pv.x * pv.x + pv.y * pv.y + pv.z * pv.z + pv.w * pv.w;
#pragma unroll
            for (int o = 16; o; o >>= 1) {
                pd += __shfl_xor_sync(~0u, pd, o);
                nn += __shfl_xor_sync(~0u, nn, o);
            }
            if (lane == 0)
                Vpsm[k][b][v] = pd * rsqrtf(nn) * scalesm[k][b];
        }
        if (wq == 0) {
            const float4 pe = __ldg((const float4*)(pos_embed + e * DK_) + lane);
            float pm = pe.x + pe.y + pe.z + pe.w;
#pragma unroll
            for (int o = 16; o; o >>= 1) pm += __shfl_xor_sync(~0u, pm, o);
            if (lane == 0) {
                float sb = 0.f, cnt = 0.f;
#pragma unroll
                for (int kk = 0; kk < 4; ++kk) {
                    const int off = (kk == 0) ? -2 : (kk == 1) ? -1 : (kk == 2) ? 1 : 2;
                    const int nb = e + off;
                    if (nb >= 0 && nb < E_) { sb += sigm(__ldg(betas + e * 4 + kk)); cnt += 1.f; }
                }
                w_esm[k] = sigm(pm * (1.0f / DK_)) * (1.0f + sb / cnt);
            }
        }
    }
    __syncthreads();   // sync3

    // -------- epilogue --------
    {
        const int b = tid >> 5;
        float den = 0.f;
        for (int kk = 0; kk < nact; ++kk) den += w_esm[kk];
        den = fmaxf(den, 1e-6f);
        float fs = 0.f;
#pragma unroll
        for (int v = 0; v < 5; ++v) {
            float nv = 0.f;
            for (int kk = 0; kk < nact; ++kk) nv += Vpsm[kk][b][v] * w_esm[kk];
            fs += nv;
        }
        const float fused = (fs / den) * 0.2f / fabsf(__ldg(temperature));

        const float* xr  = x   + ((size_t)b * P_ + p) * D_;
        float*       orw = out + ((size_t)b * P_ + p) * D_;
#pragma unroll
        for (int it = 0; it < 8; ++it) {
            const int f4 = it * 32 + lane;
            float4 xv = __ldg((const float4*)xr + f4);
            const int ee = f4 >> 4;
            const int kk = (ee == e0) ? 0 : ((ee == e1) ? 1 : -1);
            if (kk >= 0) {
                const int si = (f4 & 15) * 4;
                const float4 rv = *(const float4*)&recsm[kk][b][si];
                xv.x += fused * rv.x;
                xv.y += fused * rv.y;
                xv.z += fused * rv.z;
                xv.w += fused * rv.w;
            }
            ((float4*)orw)[f4] = xv;
        }
    }
}

} // namespace

extern "C" void kernel_launch(void* const* d_in, const int* in_sizes, int n_in,
                              void* d_out, int out_size)
{
    (void)in_sizes; (void)n_in; (void)out_size;
    repack_kernel<<<256, 256>>>(
        (const float*)d_in[9],   // wv
        (const float*)d_in[12]); // wout
    cantor_moe_kernel<<<P_, 256>>>(
        (const float*)d_in[0],   // x
        (const float*)d_in[1],   // fingerprints
        (const float*)d_in[2],   // ln_gamma
        (const float*)d_in[3],   // ln_beta
        (const float*)d_in[4],   // w1
        (const float*)d_in[5],   // b1
        (const float*)d_in[6],   // w2
        (const float*)d_in[7],   // b2
        (const float*)d_in[8],   // alpha
        (const float*)d_in[10],  // penta
        (const float*)d_in[11],  // betas
        (const float*)d_in[13],  // pos_embed
        (const float*)d_in[14],  // temperature
        (float*)d_out);
}

// round 17
// speedup vs baseline: 1.4100x; 1.0438x over previous
#include <cuda_runtime.h>
#include <math.h>
#include <stdint.h>

// CantorMoELayer — B=8, P=2048, D=1024, E=16, S=64, DK=128, H=16
// R17: exact R12 (best, 76.3us) + ONE change: __launch_bounds__(256, 5)
// (reg cap 64 -> 51). Ten rounds of profiles show occ pinned at 45% (the
// 4-CTA/64-reg ceiling) with no pipe saturated — the kernel is occupancy-
// capped latency-bound. 5 CTAs/SM -> 40 warps -> 62.5% theoretical occ.

namespace {

constexpr int P_  = 2048;
constexpr int D_  = 1024;
constexpr int E_  = 16;
constexpr int S_  = 64;
constexpr int DK_ = 128;
constexpr int H_  = 16;

constexpr int XN_STR = 68;
constexpr int V_STR  = 132;
constexpr int RC_STR = 68;

__device__ __forceinline__ float sigm(float x) { return 1.0f / (1.0f + expf(-x)); }
__device__ __forceinline__ float gelu_exact(float x) {
    return 0.5f * x * (1.0f + erff(x * 0.70710678118654752440f));
}
__device__ __forceinline__ uint32_t tf32(float f) {
    uint32_t r;
    asm("cvt.rna.tf32.f32 %0, %1;" : "=r"(r) : "f"(f));
    return r;
}
__device__ __forceinline__ void mma_m16n8k8(
    float& c0, float& c1, float& c2, float& c3,
    uint32_t a0, uint32_t a1, uint32_t a2, uint32_t a3,
    uint32_t b0, uint32_t b1)
{
    asm("mma.sync.aligned.m16n8k8.row.col.f32.tf32.tf32.f32 "
        "{%0,%1,%2,%3},{%4,%5,%6,%7},{%8,%9},{%0,%1,%2,%3};"
        : "+f"(c0), "+f"(c1), "+f"(c2), "+f"(c3)
        : "r"(a0), "r"(a1), "r"(a2), "r"(a3), "r"(b0), "r"(b1));
}

__device__ __forceinline__ void pick(float fp, int& nact, int& e0, int& e1) {
    nact = 0; e0 = 0; e1 = -1;
    const int base = (int)floorf(fp * 16.0f);
#pragma unroll
    for (int dd = -1; dd <= 1; ++dd) {
        const int ee = base + dd;
        if (ee < 0 || ee >= E_) continue;
        const float fmn = fmaxf(0.0f, (float)ee * 0.0625f - 0.03125f);
        const float fmx = fminf(1.0f, (float)(ee + 1) * 0.0625f + 0.03125f);
        if (fp >= fmn && fp < fmx) {
            if (nact == 0) e0 = ee; else if (nact == 1) e1 = ee;
            ++nact;
        }
    }
    if (nact > 2) nact = 2;
    if (nact < 2) e1 = -1;
}

// fragment-ordered TF32 weight scratch (1 MB total)
__device__ uint2 g_frag_wv[E_ * 16 * 8 * 32];
__device__ uint2 g_frag_wo[E_ * 8 * 16 * 32];

__global__ void __launch_bounds__(256) repack_kernel(
    const float* __restrict__ wv, const float* __restrict__ wout)
{
    const int i = blockIdx.x * 256 + threadIdx.x;   // 65536 threads
    const int lane = i & 31;
    const int gid = lane >> 2, tig = lane & 3;
    {   // wv: i = ((e*16 + nt)*8 + kt)*32 + lane
        const int kt = (i >> 5) & 7;
        const int nt = (i >> 8) & 15;
        const int e  = i >> 12;
        const float v0 = __ldg(wv + e * (S_ * DK_) + (kt * 8 + tig)     * DK_ + nt * 8 + gid);
        const float v1 = __ldg(wv + e * (S_ * DK_) + (kt * 8 + tig + 4) * DK_ + nt * 8 + gid);
        g_frag_wv[i] = make_uint2(tf32(v0), tf32(v1));
    }
    {   // wout: i = ((e*8 + nt)*16 + kt)*32 + lane
        const int kt = (i >> 5) & 15;
        const int nt = (i >> 9) & 7;
        const int e  = i >> 12;
        const float v0 = __ldg(wout + e * (DK_ * S_) + (kt * 8 + tig)     * S_ + nt * 8 + gid);
        const float v1 = __ldg(wout + e * (DK_ * S_) + (kt * 8 + tig + 4) * S_ + nt * 8 + gid);
        g_frag_wo[i] = make_uint2(tf32(v0), tf32(v1));
    }
}

__global__ void __launch_bounds__(256, 5) cantor_moe_kernel(
    const float* __restrict__ x,
    const float* __restrict__ fingerprints,
    const float* __restrict__ ln_gamma,
    const float* __restrict__ ln_beta,
    const float* __restrict__ w1,
    const float* __restrict__ b1,
    const float* __restrict__ w2,
    const float* __restrict__ b2,
    const float* __restrict__ alpha,
    const float* __restrict__ penta,
    const float* __restrict__ betas,
    const float* __restrict__ pos_embed,
    const float* __restrict__ temperature,
    float* __restrict__ out)
{
    __shared__ __align__(16) float xnsm[2][8][XN_STR];
    __shared__ __align__(16) float Vsm[2][8][V_STR];
    __shared__ __align__(16) float recsm[2][8][RC_STR];
    __shared__ float scalesm[2][8];
    __shared__ float Vpsm[2][8][5];
    __shared__ float w_esm[2];

    const int p    = blockIdx.x;
    const int tid  = threadIdx.x;
    const int warp = tid >> 5;
    const int lane = tid & 31;
    const int gid  = lane >> 2;
    const int tig  = lane & 3;

    int nact, e0, e1;
    pick(__ldg(fingerprints + p), nact, e0, e1);

    // ---------------- LayerNorm: warp w = batch b; 2-pass ----------------
    {
        const int b = warp;
        const float* xr = x + ((size_t)b * P_ + p) * D_;
        float s = 0.f, ss = 0.f;
#pragma unroll
        for (int it = 0; it < 8; ++it) {
            const float4 xv = __ldg((const float4*)xr + it * 32 + lane);
            s  += xv.x + xv.y + xv.z + xv.w;
            ss += xv.x * xv.x + xv.y * xv.y + xv.z * xv.z + xv.w * xv.w;
        }
#pragma unroll
        for (int o = 16; o; o >>= 1) {
            s  += __shfl_xor_sync(~0u, s, o);
            ss += __shfl_xor_sync(~0u, ss, o);
        }
        const float mu   = s * (1.0f / D_);
        const float var  = ss * (1.0f / D_) - mu * mu;
        const float rstd = rsqrtf(var + 1e-5f);
        const int kk = lane >> 4;
        if (kk < nact) {
            const int ee = kk ? e1 : e0;
            const int f4 = ee * 16 + (lane & 15);
            const float4 xv = __ldg((const float4*)xr + f4);
            const float4 gm = __ldg((const float4*)ln_gamma + f4);
            const float4 bt = __ldg((const float4*)ln_beta + f4);
            float4 o4;
            o4.x = (xv.x - mu) * rstd * gm.x + bt.x;
            o4.y = (xv.y - mu) * rstd * gm.y + bt.y;
            o4.z = (xv.z - mu) * rstd * gm.z + bt.z;
            o4.w = (xv.w - mu) * rstd * gm.w + bt.w;
            *(float4*)&xnsm[kk][b][(lane & 15) * 4] = o4;
        }
    }
    __syncthreads();   // sync1

    const int nw = (nact == 2) ? 4 : 8;
    const int k  = (nact == 2) ? (warp >> 2) : 0;
    const int wq = (nact == 2) ? (warp & 3) : warp;
    const int e  = k ? e1 : e0;

    // ---------------- gate (fp32) ----------------
    {
        const int k2 = tid >> 7, g = tid & 127;
        if (k2 < nact) {
            const int eg = k2 ? e1 : e0;
            const int b = g >> 4, j = g & 15;
            const float* W1 = w1 + eg * (S_ * H_);
            float acc = __ldg(b1 + eg * H_ + j);
#pragma unroll
            for (int s4 = 0; s4 < 16; ++s4) {
                const float4 xf = *(const float4*)&xnsm[k2][b][s4 * 4];
                acc += xf.x * __ldg(W1 + (s4 * 4 + 0) * H_ + j)
                     + xf.y * __ldg(W1 + (s4 * 4 + 1) * H_ + j)
                     + xf.z * __ldg(W1 + (s4 * 4 + 2) * H_ + j)
                     + xf.w * __ldg(W1 + (s4 * 4 + 3) * H_ + j);
            }
            float t = gelu_exact(acc) * __ldg(w2 + eg * H_ + j);
#pragma unroll
            for (int o = 8; o; o >>= 1) t += __shfl_down_sync(~0u, t, o, 16);
            if (j == 0) {
                const float gate = sigm(t + __ldg(b2 + eg));
                const float aw   = sigm(__ldg(alpha + eg));
                scalesm[k2][b] = gate * aw + (1.0f - aw);
            }
        }
    }

    // ---------------- V = feats @ wv via TF32 MMA (frag-ordered B) ----------------
    {
        uint32_t A0[8], A2[8];
#pragma unroll
        for (int kt = 0; kt < 8; ++kt) {
            A0[kt] = tf32(xnsm[k][gid][kt * 8 + tig]);
            A2[kt] = tf32(xnsm[k][gid][kt * 8 + tig + 4]);
        }
        const uint2* FWV = g_frag_wv + e * (16 * 8 * 32);
        const int ntpw = 16 / nw;
        for (int ni = 0; ni < ntpw; ++ni) {
            const int nt = wq * ntpw + ni;
            float c0 = 0.f, c1 = 0.f, c2 = 0.f, c3 = 0.f;
#pragma unroll
            for (int kt = 0; kt < 8; ++kt) {
                const uint2 bb = __ldg(FWV + (nt * 8 + kt) * 32 + lane);
                mma_m16n8k8(c0, c1, c2, c3, A0[kt], 0u, A2[kt], 0u, bb.x, bb.y);
            }
            *(float2*)&Vsm[k][gid][nt * 8 + 2 * tig] = make_float2(c0, c1);
        }
    }
    __syncthreads();   // sync2

    // ---------------- rec = V @ wout via MMA; then Vp + w_e ----------------
    {
        const uint2* FWO = g_frag_wo + e * (8 * 16 * 32);
        const float sc = scalesm[k][gid];
        const int ntpw = 8 / nw;
        for (int ni = 0; ni < ntpw; ++ni) {
            const int nt = wq * ntpw + ni;
            float c0 = 0.f, c1 = 0.f, c2 = 0.f, c3 = 0.f;
#pragma unroll
            for (int kt = 0; kt < 16; ++kt) {
                const uint32_t a0 = tf32(Vsm[k][gid][kt * 8 + tig]);
                const uint32_t a2 = tf32(Vsm[k][gid][kt * 8 + tig + 4]);
                const uint2 bb = __ldg(FWO + (nt * 16 + kt) * 32 + lane);
                mma_m16n8k8(c0, c1, c2, c3, a0, 0u, a2, 0u, bb.x, bb.y);
            }
            *(float2*)&recsm[k][gid][nt * 8 + 2 * tig] = make_float2(c0 * sc, c1 * sc);
        }

        const int dpw = 40 / nw;
        for (int t = 0; t < dpw; ++t) {
            const int idx = wq * dpw + t;
            const int v = idx >> 3, b = idx & 7;
            const float4 pv = __ldg((const float4*)(penta + (e * 5 + v) * DK_) + lane);
            const float4 vv = *(const float4*)&Vsm[k][b][lane * 4];
            float pd = pv.x * vv.x + pv.y * vv.y + pv.z * vv.z + pv.w * vv.w;
            float nn = pv.x * pv.x + pv.y * pv.y + pv.z * pv.z + pv.w * pv.w;
#pragma unroll
            for (int o = 16; o; o >>= 1) {
                pd += __shfl_xor_sync(~0u, pd, o);
                nn += __shfl_xor_sync(~0u, nn, o);
            }
            if (lane == 0)
                Vpsm[k][b][v] = pd * rsqrtf(nn) * scalesm[k][b];
        }
        if (wq == 0) {
            const float4 pe = __ldg((const float4*)(pos_embed + e * DK_) + lane);
            float pm = pe.x + pe.y + pe.z + pe.w;
#pragma unroll
            for (int o = 16; o; o >>= 1) pm += __shfl_xor_sync(~0u, pm, o);
            if (lane == 0) {
                float sb = 0.f, cnt = 0.f;
#pragma unroll
                for (int kk = 0; kk < 4; ++kk) {
                    const int off = (kk == 0) ? -2 : (kk == 1) ? -1 : (kk == 2) ? 1 : 2;
                    const int nb = e + off;
                    if (nb >= 0 && nb < E_) { sb += sigm(__ldg(betas + e * 4 + kk)); cnt += 1.f; }
                }
                w_esm[k] = sigm(pm * (1.0f / DK_)) * (1.0f + sb / cnt);
            }
        }
    }
    __syncthreads();   // sync3

    // -------- epilogue --------
    {
        const int b = tid >> 5;
        float den = 0.f;
        for (int kk = 0; kk < nact; ++kk) den += w_esm[kk];
        den = fmaxf(den, 1e-6f);
        float fs = 0.f;
#pragma unroll
        for (int v = 0; v < 5; ++v) {
            float nv = 0.f;
            for (int kk = 0; kk < nact; ++kk) nv += Vpsm[kk][b][v] * w_esm[kk];
            fs += nv;
        }
        const float fused = (fs / den) * 0.2f / fabsf(__ldg(temperature));

        const float* xr  = x   + ((size_t)b * P_ + p) * D_;
        float*       orw = out + ((size_t)b * P_ + p) * D_;
#pragma unroll
        for (int it = 0; it < 8; ++it) {
            const int f4 = it * 32 + lane;
            float4 xv = __ldg((const float4*)xr + f4);
            const int ee = f4 >> 4;
            const int kk = (ee == e0) ? 0 : ((ee == e1) ? 1 : -1);
            if (kk >= 0) {
                const int si = (f4 & 15) * 4;
                const float4 rv = *(const float4*)&recsm[kk][b][si];
                xv.x += fused * rv.x;
                xv.y += fused * rv.y;
                xv.z += fused * rv.z;
                xv.w += fused * rv.w;
            }
            ((float4*)orw)[f4] = xv;
        }
    }
}

} // namespace

extern "C" void kernel_launch(void* const* d_in, const int* in_sizes, int n_in,
                              void* d_out, int out_size)
{
    (void)in_sizes; (void)n_in; (void)out_size;
    repack_kernel<<<256, 256>>>(
        (const float*)d_in[9],   // wv
        (const float*)d_in[12]); // wout
    cantor_moe_kernel<<<P_, 256>>>(
        (const float*)d_in[0],   // x
        (const float*)d_in[1],   // fingerprints
        (const float*)d_in[2],   // ln_gamma
        (const float*)d_in[3],   // ln_beta
        (const float*)d_in[4],   // w1
        (const float*)d_in[5],   // b1
        (const float*)d_in[6],   // w2
        (const float*)d_in[7],   // b2
        (const float*)d_in[8],   // alpha
        (const float*)d_in[10],  // penta
        (const float*)d_in[11],  // betas
        (const float*)d_in[13],  // pos_embed
        (const float*)d_in[14],  // temperature
        (float*)d_out);
}